// round 1
// baseline (speedup 1.0000x reference)
#include <cuda_runtime.h>
#include <cstdint>

#define HD    1024
#define DIN   512
#define KTOT  1536          // DIN + HD
#define BATCH 64
#define LSEQ  512
#define NGATE 4096          // 4*HD
#define ZPAD  68            // padded row stride (floats) for z staging

// ---------------- static device scratch (no allocations allowed) ----------------
__device__ float g_WT4[(KTOT / 4) * NGATE * 4]; // [kq][col][4] interleaved k-quads
__device__ float g_h[2][BATCH * HD];            // double-buffered hidden state
__device__ float g_c[BATCH * HD];               // cell state

// ---------------- f32x2 packed-FMA helpers (sm_100+ PTX) ----------------
__device__ __forceinline__ void fma2(unsigned long long& d,
                                     unsigned long long a,
                                     unsigned long long b) {
    asm("fma.rn.f32x2 %0, %1, %2, %0;" : "+l"(d) : "l"(a), "l"(b));
}
__device__ __forceinline__ unsigned long long pack2(float x, float y) {
    unsigned long long r;
    asm("mov.b64 %0, {%1, %2};" : "=l"(r) : "f"(x), "f"(y));
    return r;
}
__device__ __forceinline__ float2 unpack2(unsigned long long v) {
    float2 r;
    asm("mov.b64 {%0, %1}, %2;" : "=f"(r.x), "=f"(r.y) : "l"(v));
    return r;
}

// ---------------- prep: build interleaved transposed weights ----------------
// WT4[(k>>2)*NGATE*4 + col*4 + (k&3)] = W_gate[j][k],  col = gate*HD + j
__global__ void prep_wt4(const float* __restrict__ Wf, const float* __restrict__ Wi,
                         const float* __restrict__ Wc, const float* __restrict__ Wo) {
    int idx = blockIdx.x * 256 + threadIdx.x;
    if (idx >= KTOT * NGATE) return;
    int kq  = idx >> 14;          // / (NGATE*4)
    int rem = idx & 16383;
    int col = rem >> 2;
    int klo = rem & 3;
    int k   = kq * 4 + klo;
    int gate = col >> 10;
    int j    = col & 1023;
    const float* W = (gate == 0) ? Wf : (gate == 1) ? Wi : (gate == 2) ? Wc : Wo;
    g_WT4[idx] = W[j * KTOT + k];
}

__global__ void prep_zero() {
    int idx = blockIdx.x * 256 + threadIdx.x;
    if (idx < BATCH * HD) {
        g_h[0][idx] = 0.f;
        g_h[1][idx] = 0.f;
        g_c[idx]    = 0.f;
    }
}

// ---------------- one LSTM timestep ----------------
// grid = 128 CTAs (each owns hidden slice of 8), block = 256 threads
__global__ __launch_bounds__(256, 1) void lstm_step(
    int t, int cur,
    const int*   __restrict__ x,
    const float* __restrict__ emb,
    const float* __restrict__ bf, const float* __restrict__ bi,
    const float* __restrict__ bc, const float* __restrict__ bo,
    float* __restrict__ out) {

    __shared__ float z_s[2][64 * ZPAD];   // double-buffered z chunk [row][k]
    __shared__ int   tok_s[64];
    __shared__ float g_s[64][33];         // gate pre-activations [row][lane-col]

    const int tid  = threadIdx.x;
    const int lane = tid & 31;
    const int warp = tid >> 5;
    const int j0   = blockIdx.x * 8;
    const int gate = lane >> 3;
    const int jj   = lane & 7;
    const int col  = gate * HD + j0 + jj;   // gate column in [0,4096)
    const int r0   = warp * 8;              // batch rows for this warp

    if (tid < 64) tok_s[tid] = x[t * BATCH + tid];
    __syncthreads();

    // staging roles: 256 threads load a 64x64 fp32 chunk
    const int sr = tid >> 2;        // row 0..63
    const int sq = tid & 3;         // quarter 0..3 -> 16 k's each
    const int kbase = sq * 16;

    const float* hcur = g_h[cur];
    float*       hnxt = g_h[cur ^ 1];

    // accumulators: one packed f32x2 per batch row (even/odd k partial sums)
    const float* bp = (gate == 0) ? bf : (gate == 1) ? bi : (gate == 2) ? bc : bo;
    const float bias = bp[j0 + jj];
    unsigned long long acc[8];
#pragma unroll
    for (int i = 0; i < 8; i++) acc[i] = pack2(bias, 0.f);

    // prefetch chunk 0 (pure embedding region)
    float4 v[4];
    {
        const float* src = emb + (size_t)tok_s[sr] * DIN + kbase;
#pragma unroll
        for (int ii = 0; ii < 4; ii++) v[ii] = *(const float4*)(src + ii * 4);
    }

    const float* wbase = g_WT4 + (size_t)col * 4;
    const int nchunk = KTOT / 64;   // 24

    for (int c = 0; c < nchunk; c++) {
        float* zb = z_s[c & 1];
        // commit prefetched chunk to SMEM
#pragma unroll
        for (int ii = 0; ii < 4; ii++)
            *(float4*)(zb + sr * ZPAD + kbase + ii * 4) = v[ii];
        __syncthreads();

        // prefetch next chunk (hidden latency under compute below)
        if (c + 1 < nchunk) {
            const int kc = (c + 1) * 64;
            const float* src = (kc < DIN)
                ? (emb + (size_t)tok_s[sr] * DIN + kc + kbase)
                : (hcur + sr * HD + (kc - DIN) + kbase);
#pragma unroll
            for (int ii = 0; ii < 4; ii++) v[ii] = *(const float4*)(src + ii * 4);
        }

        // compute: 16 k-quads over this chunk
        const float* wq   = wbase + (size_t)c * 16 * (NGATE * 4);
        const float* zrow = zb + r0 * ZPAD;
#pragma unroll
        for (int kk = 0; kk < 64; kk += 4) {
            ulonglong2 wv = *(const ulonglong2*)wq;   // 4 weights for this col
            wq += NGATE * 4;
#pragma unroll
            for (int i = 0; i < 8; i++) {
                ulonglong2 zv = *(const ulonglong2*)(zrow + i * ZPAD + kk);
                fma2(acc[i], zv.x, wv.x);
                fma2(acc[i], zv.y, wv.y);
            }
        }
        __syncthreads();
    }

    // gate pre-activations -> SMEM
#pragma unroll
    for (int i = 0; i < 8; i++) {
        float2 s = unpack2(acc[i]);
        g_s[r0 + i][lane] = s.x + s.y;
    }
    __syncthreads();

    // elementwise state update: 512 (row, j) elements, 2 per thread
#pragma unroll
    for (int u = 0; u < 2; u++) {
        int id = tid + u * 256;
        int r  = id >> 3;
        int jx = id & 7;
        float gf = g_s[r][jx];
        float gi = g_s[r][jx + 8];
        float gc = g_s[r][jx + 16];
        float go = g_s[r][jx + 24];
        float f  = 1.f / (1.f + __expf(-gf));
        float i_ = 1.f / (1.f + __expf(-gi));
        float o  = 1.f / (1.f + __expf(-go));
        int jg   = j0 + jx;
        float cold = g_c[r * HD + jg];
        float cnew = f * cold + i_ * tanhf(gc);
        float h    = o * tanhf(cnew);
        g_c[r * HD + jg]  = cnew;
        hnxt[r * HD + jg] = h;
        out[((size_t)t * BATCH + r) * HD + jg] = h;
        if (t == LSEQ - 1) {
            size_t base = (size_t)LSEQ * BATCH * HD;
            out[base + r * HD + jg] = cnew;                   // final c
            out[base + BATCH * HD + r * HD + jg] = h;         // final h
        }
    }
}

extern "C" void kernel_launch(void* const* d_in, const int* in_sizes, int n_in,
                              void* d_out, int out_size) {
    const int*   x   = (const int*)d_in[0];
    const float* emb = (const float*)d_in[1];
    const float* Wf  = (const float*)d_in[2];
    const float* bf  = (const float*)d_in[3];
    const float* Wi  = (const float*)d_in[4];
    const float* bi  = (const float*)d_in[5];
    const float* Wc  = (const float*)d_in[6];
    const float* bc  = (const float*)d_in[7];
    const float* Wo  = (const float*)d_in[8];
    const float* bo  = (const float*)d_in[9];
    float* out = (float*)d_out;

    prep_wt4<<<(KTOT * NGATE + 255) / 256, 256>>>(Wf, Wi, Wc, Wo);
    prep_zero<<<(BATCH * HD + 255) / 256, 256>>>();

    for (int t = 0; t < LSEQ; t++) {
        lstm_step<<<128, 256>>>(t, t & 1, x, emb, bf, bi, bc, bo, out);
    }
}

// round 2
// speedup vs baseline: 1.5666x; 1.5666x over previous
#include <cuda_runtime.h>
#include <cstdint>

#define HD    1024
#define DIN   512
#define KTOT  1536          // DIN + HD
#define BATCH 64
#define LSEQ  512
#define NGATE 4096          // 4*HD
#define ZPAD  68            // padded row stride (floats) for z staging

// ---------------- static device scratch (no allocations allowed) ----------------
__device__ float g_WT4[(KTOT / 4) * NGATE * 4]; // [kq][col][4] interleaved k-quads
__device__ float g_h[2][BATCH * HD];            // double-buffered hidden state
__device__ float g_c[BATCH * HD];               // cell state

// ---------------- f32x2 packed-FMA helpers (sm_100+ PTX) ----------------
__device__ __forceinline__ void fma2(unsigned long long& d,
                                     unsigned long long a,
                                     unsigned long long b) {
    asm("fma.rn.f32x2 %0, %1, %2, %0;" : "+l"(d) : "l"(a), "l"(b));
}
__device__ __forceinline__ unsigned long long pack2(float x, float y) {
    unsigned long long r;
    asm("mov.b64 %0, {%1, %2};" : "=l"(r) : "f"(x), "f"(y));
    return r;
}
__device__ __forceinline__ float2 unpack2(unsigned long long v) {
    float2 r;
    asm("mov.b64 {%0, %1}, %2;" : "=f"(r.x), "=f"(r.y) : "l"(v));
    return r;
}

// ---------------- prep: build interleaved transposed weights ----------------
// WT4[(k>>2)*NGATE*4 + col*4 + (k&3)] = W_gate[j][k],  col = gate*HD + j
__global__ void prep_wt4(const float* __restrict__ Wf, const float* __restrict__ Wi,
                         const float* __restrict__ Wc, const float* __restrict__ Wo) {
    int idx = blockIdx.x * 256 + threadIdx.x;
    if (idx >= KTOT * NGATE) return;
    int kq  = idx >> 14;          // / (NGATE*4)
    int rem = idx & 16383;
    int col = rem >> 2;
    int klo = rem & 3;
    int k   = kq * 4 + klo;
    int gate = col >> 10;
    int j    = col & 1023;
    const float* W = (gate == 0) ? Wf : (gate == 1) ? Wi : (gate == 2) ? Wc : Wo;
    g_WT4[idx] = W[j * KTOT + k];
}

__global__ void prep_zero() {
    int idx = blockIdx.x * 256 + threadIdx.x;
    if (idx < BATCH * HD) {
        g_h[0][idx] = 0.f;
        g_h[1][idx] = 0.f;
        g_c[idx]    = 0.f;
    }
}

// ---------------- one LSTM timestep ----------------
// grid = 128 CTAs (each owns hidden slice of 8), block = 256 threads
__global__ __launch_bounds__(256, 1) void lstm_step(
    int t, int cur,
    const int*   __restrict__ x,
    const float* __restrict__ emb,
    const float* __restrict__ bf, const float* __restrict__ bi,
    const float* __restrict__ bc, const float* __restrict__ bo,
    float* __restrict__ out) {

    __shared__ float z_s[2][64 * ZPAD];   // double-buffered z chunk [row][k]
    __shared__ int   tok_s[64];
    __shared__ float g_s[64][33];         // gate pre-activations [row][lane-col]

    const int tid  = threadIdx.x;
    const int lane = tid & 31;
    const int warp = tid >> 5;
    const int j0   = blockIdx.x * 8;
    const int gate = lane >> 3;
    const int jj   = lane & 7;
    const int col  = gate * HD + j0 + jj;   // gate column in [0,4096)
    const int r0   = warp * 8;              // batch rows for this warp

    if (tid < 64) tok_s[tid] = x[t * BATCH + tid];
    __syncthreads();

    // staging roles: 256 threads load a 64x64 fp32 chunk
    const int sr = tid >> 2;        // row 0..63
    const int sq = tid & 3;         // quarter 0..3 -> 16 k's each
    const int kbase = sq * 16;

    const float* hcur = g_h[cur];
    float*       hnxt = g_h[cur ^ 1];

    // accumulators: one packed f32x2 per batch row (even/odd k partial sums)
    const float* bp = (gate == 0) ? bf : (gate == 1) ? bi : (gate == 2) ? bc : bo;
    const float bias = bp[j0 + jj];
    unsigned long long acc[8];
#pragma unroll
    for (int i = 0; i < 8; i++) acc[i] = pack2(bias, 0.f);

    // prefetch chunk 0 (pure embedding region)
    float4 v[4];
    {
        const float* src = emb + (size_t)tok_s[sr] * DIN + kbase;
#pragma unroll
        for (int ii = 0; ii < 4; ii++) v[ii] = *(const float4*)(src + ii * 4);
    }

    const float* wbase = g_WT4 + (size_t)col * 4;
    const int nchunk = KTOT / 64;   // 24

    for (int c = 0; c < nchunk; c++) {
        float* zb = z_s[c & 1];
        // commit prefetched chunk to SMEM
#pragma unroll
        for (int ii = 0; ii < 4; ii++)
            *(float4*)(zb + sr * ZPAD + kbase + ii * 4) = v[ii];
        __syncthreads();

        // prefetch next chunk (hidden latency under compute below)
        if (c + 1 < nchunk) {
            const int kc = (c + 1) * 64;
            const float* src = (kc < DIN)
                ? (emb + (size_t)tok_s[sr] * DIN + kc + kbase)
                : (hcur + sr * HD + (kc - DIN) + kbase);
#pragma unroll
            for (int ii = 0; ii < 4; ii++) v[ii] = *(const float4*)(src + ii * 4);
        }

        // compute: 16 k-quads over this chunk
        const float* wq   = wbase + (size_t)c * 16 * (NGATE * 4);
        const float* zrow = zb + r0 * ZPAD;
#pragma unroll
        for (int kk = 0; kk < 64; kk += 4) {
            ulonglong2 wv = *(const ulonglong2*)wq;   // 4 weights for this col
            wq += NGATE * 4;
#pragma unroll
            for (int i = 0; i < 8; i++) {
                ulonglong2 zv = *(const ulonglong2*)(zrow + i * ZPAD + kk);
                fma2(acc[i], zv.x, wv.x);
                fma2(acc[i], zv.y, wv.y);
            }
        }
        __syncthreads();
    }

    // gate pre-activations -> SMEM
#pragma unroll
    for (int i = 0; i < 8; i++) {
        float2 s = unpack2(acc[i]);
        g_s[r0 + i][lane] = s.x + s.y;
    }
    __syncthreads();

    // elementwise state update: 512 (row, j) elements, 2 per thread
#pragma unroll
    for (int u = 0; u < 2; u++) {
        int id = tid + u * 256;
        int r  = id >> 3;
        int jx = id & 7;
        float gf = g_s[r][jx];
        float gi = g_s[r][jx + 8];
        float gc = g_s[r][jx + 16];
        float go = g_s[r][jx + 24];
        float f  = 1.f / (1.f + __expf(-gf));
        float i_ = 1.f / (1.f + __expf(-gi));
        float o  = 1.f / (1.f + __expf(-go));
        int jg   = j0 + jx;
        float cold = g_c[r * HD + jg];
        float cnew = f * cold + i_ * tanhf(gc);
        float h    = o * tanhf(cnew);
        g_c[r * HD + jg]  = cnew;
        hnxt[r * HD + jg] = h;
        out[((size_t)t * BATCH + r) * HD + jg] = h;
        if (t == LSEQ - 1) {
            size_t base = (size_t)LSEQ * BATCH * HD;
            out[base + r * HD + jg] = cnew;                   // final c
            out[base + BATCH * HD + r * HD + jg] = h;         // final h
        }
    }
}

extern "C" void kernel_launch(void* const* d_in, const int* in_sizes, int n_in,
                              void* d_out, int out_size) {
    const int*   x   = (const int*)d_in[0];
    const float* emb = (const float*)d_in[1];
    const float* Wf  = (const float*)d_in[2];
    const float* bf  = (const float*)d_in[3];
    const float* Wi  = (const float*)d_in[4];
    const float* bi  = (const float*)d_in[5];
    const float* Wc  = (const float*)d_in[6];
    const float* bc  = (const float*)d_in[7];
    const float* Wo  = (const float*)d_in[8];
    const float* bo  = (const float*)d_in[9];
    float* out = (float*)d_out;

    prep_wt4<<<(KTOT * NGATE + 255) / 256, 256>>>(Wf, Wi, Wc, Wo);
    prep_zero<<<(BATCH * HD + 255) / 256, 256>>>();

    for (int t = 0; t < LSEQ; t++) {
        lstm_step<<<128, 256>>>(t, t & 1, x, emb, bf, bi, bc, bo, out);
    }
}

// round 5
// speedup vs baseline: 3.1761x; 2.0274x over previous
#include <cuda_runtime.h>
#include <cuda_bf16.h>
#include <cstdint>

#define HD     1024
#define DIN    512
#define KTOT   1536
#define BATCH  64
#define LSEQ   512
#define NCTA   64
#define NCHUNK 24                       // K chunks of 64
#define TILE_ELEMS 4096                 // 64x64 bf16 tile
#define TILE_BYTES 8192
#define STAGE_BYTES (4*TILE_BYTES)      // Ahi|Alo|Bhi|Blo = 32768
#define NSTAGE 3
#define CHUNK_TX 32768u
#define SMEM_DYN (NSTAGE*STAGE_BYTES + 1024 + 64)

#define WSPLIT (64u*24*TILE_ELEMS)      // g_Wimg split stride (elems)
#define XSPLIT (512u*8*TILE_ELEMS)

// ---------------- static device scratch ----------------
__device__ __nv_bfloat16 g_Wimg[2u*64*24*TILE_ELEMS];  // [split][cta][chunk][swizzled 64x64]
__device__ __nv_bfloat16 g_Ximg[2u*512*8*TILE_ELEMS];  // [split][t][chunk][swizzled 64x64]
__device__ __nv_bfloat16 g_Himg[2u*2*16*TILE_ELEMS];   // [split][buf][chunk][swizzled 64x64]
__device__ float g_c[BATCH*HD];

// ---------------- helpers ----------------
__device__ __forceinline__ uint32_t smem_u32(const void* p) {
    uint32_t a;
    asm("{ .reg .u64 t; cvta.to.shared.u64 t, %1; cvt.u32.u64 %0, t; }" : "=r"(a) : "l"(p));
    return a;
}
__host__ __device__ __forceinline__ uint32_t sw128(uint32_t o) {
    return o ^ ((o >> 3) & 0x70);
}
__device__ __forceinline__ void mb_init(uint32_t a) {
    asm volatile("mbarrier.init.shared.b64 [%0], %1;" :: "r"(a), "r"(1u) : "memory");
}
__device__ __forceinline__ void mb_expect(uint32_t a, uint32_t bytes) {
    asm volatile("mbarrier.arrive.expect_tx.shared.b64 _, [%0], %1;" :: "r"(a), "r"(bytes) : "memory");
}
__device__ __forceinline__ void mb_wait(uint32_t a, uint32_t ph) {
    asm volatile(
        "{\n\t.reg .pred P;\n\t"
        "WL_%=:\n\t"
        "mbarrier.try_wait.parity.acquire.cta.shared::cta.b64 P, [%0], %1, 0x989680;\n\t"
        "@P bra.uni WD_%=;\n\t"
        "bra.uni WL_%=;\n\t"
        "WD_%=:\n\t}"
        :: "r"(a), "r"(ph) : "memory");
}
__device__ __forceinline__ void bulk_g2s(uint32_t dst, const void* src, uint32_t bytes, uint32_t mb) {
    asm volatile(
        "cp.async.bulk.shared::cta.global.mbarrier::complete_tx::bytes [%0], [%1], %2, [%3];"
        :: "r"(dst), "l"((unsigned long long)__cvta_generic_to_global(src)),
           "r"(bytes), "r"(mb) : "memory");
}
__device__ __forceinline__ void ldsm4(uint32_t* r, uint32_t addr) {
    asm volatile("ldmatrix.sync.aligned.m8n8.x4.shared.b16 {%0,%1,%2,%3}, [%4];"
                 : "=r"(r[0]), "=r"(r[1]), "=r"(r[2]), "=r"(r[3]) : "r"(addr));
}
__device__ __forceinline__ void mma_bf16(float* d, const uint32_t* a, const uint32_t* b) {
    asm volatile(
        "mma.sync.aligned.m16n8k16.row.col.f32.bf16.bf16.f32 "
        "{%0,%1,%2,%3}, {%4,%5,%6,%7}, {%8,%9}, {%0,%1,%2,%3};"
        : "+f"(d[0]), "+f"(d[1]), "+f"(d[2]), "+f"(d[3])
        : "r"(a[0]), "r"(a[1]), "r"(a[2]), "r"(a[3]), "r"(b[0]), "r"(b[1]));
}

// ---------------- prep kernels ----------------
__global__ void prep_w(const float* __restrict__ Wf, const float* __restrict__ Wi,
                       const float* __restrict__ Wc, const float* __restrict__ Wo) {
    uint32_t idx = blockIdx.x * 256 + threadIdx.x;
    if (idx >= 64u * 24 * 64 * 64) return;
    uint32_t kcol = idx & 63;
    uint32_t rloc = (idx >> 6) & 63;
    uint32_t t2   = idx >> 12;
    uint32_t c    = t2 % 24;
    uint32_t b    = t2 / 24;
    uint32_t j    = b * 16 + (rloc >> 2);
    uint32_t gate = rloc & 3;
    uint32_t k    = c * 64 + kcol;
    const float* W = (gate == 0) ? Wf : (gate == 1) ? Wi : (gate == 2) ? Wc : Wo;
    float w = W[j * KTOT + k];
    __nv_bfloat16 hi = __float2bfloat16(w);
    __nv_bfloat16 lo = __float2bfloat16(w - __bfloat162float(hi));
    uint32_t e = sw128(rloc * 128 + kcol * 2) >> 1;
    uint32_t tile = (b * 24 + c) * TILE_ELEMS;
    g_Wimg[tile + e] = hi;
    g_Wimg[WSPLIT + tile + e] = lo;
}

__global__ void prep_x(const int* __restrict__ x, const float* __restrict__ emb) {
    uint32_t idx = blockIdx.x * 256 + threadIdx.x;
    if (idx >= 512u * 8 * 64 * 64) return;
    uint32_t kcol = idx & 63;
    uint32_t n    = (idx >> 6) & 63;
    uint32_t c    = (idx >> 12) & 7;
    uint32_t t    = idx >> 15;
    int tok = x[t * BATCH + n];
    float v = emb[(size_t)tok * DIN + c * 64 + kcol];
    __nv_bfloat16 hi = __float2bfloat16(v);
    __nv_bfloat16 lo = __float2bfloat16(v - __bfloat162float(hi));
    uint32_t e = sw128(n * 128 + kcol * 2) >> 1;
    uint32_t off = (t * 8 + c) * TILE_ELEMS;
    g_Ximg[off + e] = hi;
    g_Ximg[XSPLIT + off + e] = lo;
}

__global__ void prep_zero() {
    uint32_t idx = blockIdx.x * 256 + threadIdx.x;
    if (idx < 2u * 2 * 16 * TILE_ELEMS) g_Himg[idx] = __float2bfloat16(0.f);
    if (idx < BATCH * HD) g_c[idx] = 0.f;
}

// ---------------- one LSTM timestep ----------------
// grid 64 CTAs (M=64 gate-rows each = 16 j x 4 gates), 128 threads (4 warps, 32x32 tiles)
__global__ __launch_bounds__(128, 1) void lstm_step(
    int t,
    const float* __restrict__ bfp, const float* __restrict__ bip,
    const float* __restrict__ bcp, const float* __restrict__ bop,
    float* __restrict__ out) {

    extern __shared__ char smem_raw[];
    uint32_t sb0 = smem_u32(smem_raw);
    uint32_t sb  = (sb0 + 1023) & ~1023u;
    char* smem_al = smem_raw + (sb - sb0);

    const int tid = threadIdx.x;
    const int wid = tid >> 5;
    const int lid = tid & 31;
    const int b   = blockIdx.x;
    const int wm  = wid & 1;      // m-warp
    const int wn  = wid >> 1;     // n-warp
    const int m0  = wm * 32;
    const int n0w = wn * 32;

    const uint32_t barBase = sb + NSTAGE * STAGE_BYTES;

    if (tid == 0) {
        for (int s = 0; s < NSTAGE; s++) mb_init(barBase + s * 8);
    }
    __syncthreads();

    const int wbuf = t & 1;
    const int rbuf = wbuf ^ 1;

    // accumulators: 2 m-tiles x 4 n-tiles x 4 regs
    float acc[8][4];
#pragma unroll
    for (int i = 0; i < 8; i++)
#pragma unroll
        for (int q = 0; q < 4; q++) acc[i][q] = 0.f;

    // issue loads for a chunk (tid 0 only)
    auto issue_load = [&](int c) {
        uint32_t s   = c % 3;
        uint32_t stg = sb + s * STAGE_BYTES;
        uint32_t mb  = barBase + s * 8;
        mb_expect(mb, CHUNK_TX);
        const __nv_bfloat16* aH = g_Wimg + (size_t)(b * 24 + c) * TILE_ELEMS;
        const __nv_bfloat16* aL = aH + WSPLIT;
        const __nv_bfloat16 *bH, *bL;
        if (c < 8) {
            bH = g_Ximg + (size_t)(t * 8 + c) * TILE_ELEMS;
            bL = bH + XSPLIT;
        } else {
            bH = g_Himg + (size_t)((0 * 2 + rbuf) * 16 + (c - 8)) * TILE_ELEMS;
            bL = g_Himg + (size_t)((1 * 2 + rbuf) * 16 + (c - 8)) * TILE_ELEMS;
        }
        bulk_g2s(stg,                 aH, TILE_BYTES, mb);
        bulk_g2s(stg + TILE_BYTES,    aL, TILE_BYTES, mb);
        bulk_g2s(stg + 2*TILE_BYTES,  bH, TILE_BYTES, mb);
        bulk_g2s(stg + 3*TILE_BYTES,  bL, TILE_BYTES, mb);
    };

    if (tid == 0) { issue_load(0); issue_load(1); }

    // precomputed (swizzled) lane offsets
    const uint32_t arow  = (uint32_t)(lid & 15);
    const uint32_t acolb = ((uint32_t)(lid >> 4)) * 16;
    const uint32_t brow  = (uint32_t)(n0w + ((lid >> 4) << 3) + (lid & 7));
    const uint32_t bkb   = (uint32_t)(((lid >> 3) & 1) << 4);

    for (int c = 0; c < NCHUNK; c++) {
        if (tid == 0 && c + 2 < NCHUNK) issue_load(c + 2);
        mb_wait(barBase + (c % 3) * 8, (c / 3) & 1);

        uint32_t stg = sb + (c % 3) * STAGE_BYTES;
        uint32_t aHb = stg, aLb = stg + TILE_BYTES;
        uint32_t bHb = stg + 2*TILE_BYTES, bLb = stg + 3*TILE_BYTES;

#pragma unroll
        for (int kk = 0; kk < 4; kk++) {
            uint32_t ak = kk * 32 + acolb;
            uint32_t bk = kk * 32 + bkb;
            uint32_t aoff0 = sw128((m0 + arow) * 128 + ak);
            uint32_t aoff1 = sw128((m0 + 16 + arow) * 128 + ak);
            uint32_t boff0 = sw128(brow * 128 + bk);
            uint32_t boff1 = sw128((brow + 16) * 128 + bk);

            uint32_t ah[8], al[8], bh[8], bl[8];
            ldsm4(ah,     aHb + aoff0);
            ldsm4(ah + 4, aHb + aoff1);
            ldsm4(al,     aLb + aoff0);
            ldsm4(al + 4, aLb + aoff1);
            ldsm4(bh,     bHb + boff0);
            ldsm4(bh + 4, bHb + boff1);
            ldsm4(bl,     bLb + boff0);
            ldsm4(bl + 4, bLb + boff1);

#pragma unroll
            for (int mt = 0; mt < 2; mt++) {
                const uint32_t* aH4 = ah + mt * 4;
                const uint32_t* aL4 = al + mt * 4;
#pragma unroll
                for (int nt = 0; nt < 4; nt++) {
                    float* d = acc[mt * 4 + nt];
                    const uint32_t* bH2 = bh + nt * 2;
                    const uint32_t* bL2 = bl + nt * 2;
                    mma_bf16(d, aH4, bH2);
                    mma_bf16(d, aH4, bL2);
                    mma_bf16(d, aL4, bH2);
                }
            }
        }
        __syncthreads();
    }

    // ---------- epilogue ----------
    float* gs = (float*)smem_al;     // [64 rows][65] fp32
    {
        int rr = lid >> 2;
        int cc0 = (lid & 3) * 2;
#pragma unroll
        for (int mt = 0; mt < 2; mt++)
#pragma unroll
            for (int nt = 0; nt < 4; nt++) {
                float* d = acc[mt * 4 + nt];
                int r = m0 + mt * 16 + rr;
                int cc = n0w + nt * 8 + cc0;
                gs[r * 65 + cc]           = d[0];
                gs[r * 65 + cc + 1]       = d[1];
                gs[(r + 8) * 65 + cc]     = d[2];
                gs[(r + 8) * 65 + cc + 1] = d[3];
            }
    }
    __syncthreads();

    // state update: 16 j x 64 n per CTA
#pragma unroll
    for (int u = 0; u < 8; u++) {
        int id = u * 128 + tid;
        int n  = id & 63;
        int jl = id >> 6;
        int jg = b * 16 + jl;
        float pf = gs[(jl * 4 + 0) * 65 + n] + bfp[jg];
        float pi = gs[(jl * 4 + 1) * 65 + n] + bip[jg];
        float pc = gs[(jl * 4 + 2) * 65 + n] + bcp[jg];
        float po = gs[(jl * 4 + 3) * 65 + n] + bop[jg];
        float f  = 1.f / (1.f + __expf(-pf));
        float i_ = 1.f / (1.f + __expf(-pi));
        float o  = 1.f / (1.f + __expf(-po));
        float cold = g_c[n * HD + jg];
        float cnew = f * cold + i_ * tanhf(pc);
        float h    = o * tanhf(cnew);
        g_c[n * HD + jg] = cnew;
        out[((size_t)t * BATCH + n) * HD + jg] = h;
        if (t == LSEQ - 1) {
            size_t base = (size_t)LSEQ * BATCH * HD;
            out[base + n * HD + jg] = cnew;
            out[base + BATCH * HD + n * HD + jg] = h;
        }
        __nv_bfloat16 hh = __float2bfloat16(h);
        __nv_bfloat16 hl = __float2bfloat16(h - __bfloat162float(hh));
        uint32_t ci = (uint32_t)jg >> 6, kcol = (uint32_t)jg & 63;
        uint32_t e  = sw128((uint32_t)n * 128 + kcol * 2) >> 1;
        g_Himg[((0u * 2 + wbuf) * 16 + ci) * TILE_ELEMS + e] = hh;
        g_Himg[((1u * 2 + wbuf) * 16 + ci) * TILE_ELEMS + e] = hl;
    }
}

extern "C" void kernel_launch(void* const* d_in, const int* in_sizes, int n_in,
                              void* d_out, int out_size) {
    const int*   x   = (const int*)d_in[0];
    const float* emb = (const float*)d_in[1];
    const float* Wf  = (const float*)d_in[2];
    const float* bf  = (const float*)d_in[3];
    const float* Wi  = (const float*)d_in[4];
    const float* bi  = (const float*)d_in[5];
    const float* Wc  = (const float*)d_in[6];
    const float* bc  = (const float*)d_in[7];
    const float* Wo  = (const float*)d_in[8];
    const float* bo  = (const float*)d_in[9];
    float* out = (float*)d_out;

    static bool attr_set = false;
    if (!attr_set) {
        cudaFuncSetAttribute(lstm_step, cudaFuncAttributeMaxDynamicSharedMemorySize, SMEM_DYN);
        attr_set = true;
    }

    prep_w<<<(64u * 24 * 64 * 64 + 255) / 256, 256>>>(Wf, Wi, Wc, Wo);
    prep_x<<<(512u * 8 * 64 * 64 + 255) / 256, 256>>>(x, emb);
    prep_zero<<<(2u * 2 * 16 * TILE_ELEMS + 255) / 256, 256>>>();

    for (int t = 0; t < LSEQ; t++) {
        lstm_step<<<NCTA, 128, SMEM_DYN>>>(t, bf, bi, bc, bo, out);
    }
}